// round 16
// baseline (speedup 1.0000x reference)
#include <cuda_runtime.h>
#include <cuda_fp16.h>
#include <cstdint>

#define N_TOK 4096
#define D_MODEL 512
#define NH 8
#define DH 64
#define HP 72       // flash fp16 smem row pitch (halves)
#define GPH 40      // gemm fp16 smem row pitch (halves)
#define SMAX 16.0f  // static softmax max (log2 domain)
#define KBUF (64 * HP)          // halves per K/V buffer
#define KBUFB (KBUF * 2)        // bytes per buffer (9216)

// ---- device scratch (no cudaMalloc allowed) ----
__device__ __half g_xh[(size_t)N_TOK * D_MODEL];
__device__ __half g_Wh[4][(size_t)D_MODEL * D_MODEL];   // Wq, Wk, Wv, Wo
__device__ __half g_Qh[(size_t)N_TOK * D_MODEL];        // pre-scaled by qscale
__device__ __half g_Kh[(size_t)N_TOK * D_MODEL];
__device__ __half g_Vh[(size_t)N_TOK * D_MODEL];
__device__ __half g_AOh[(size_t)N_TOK * D_MODEL];
__device__ __half g_distH[(size_t)N_TOK * N_TOK];       // lane-ordered fp16 distances

// ============================================================
// helpers
// ============================================================
__device__ __forceinline__ float ex2f(float x) {
    float y;
    asm("ex2.approx.f32 %0, %1;" : "=f"(y) : "f"(x));
    return y;
}
__device__ __forceinline__ float sqrt_ap(float x) {
    float y;
    asm("sqrt.approx.f32 %0, %1;" : "=f"(y) : "f"(x));
    return y;
}
__device__ __forceinline__ unsigned h2u(float x, float y) {
    __half2 h = __floats2half2_rn(x, y);
    return *reinterpret_cast<unsigned*>(&h);
}

// fp16 m16n8k16, fp32 accum
__device__ __forceinline__ void mma_f16(float d[4],
    unsigned a0, unsigned a1, unsigned a2, unsigned a3,
    unsigned b0, unsigned b1) {
    asm volatile(
        "mma.sync.aligned.m16n8k16.row.col.f32.f16.f16.f32 "
        "{%0,%1,%2,%3},{%4,%5,%6,%7},{%8,%9},{%0,%1,%2,%3};\n"
        : "+f"(d[0]), "+f"(d[1]), "+f"(d[2]), "+f"(d[3])
        : "r"(a0), "r"(a1), "r"(a2), "r"(a3), "r"(b0), "r"(b1));
}

__device__ __forceinline__ void ldsm4(unsigned& r0, unsigned& r1, unsigned& r2, unsigned& r3,
                                      uint32_t addr) {
    asm volatile("ldmatrix.sync.aligned.m8n8.x4.shared.b16 {%0,%1,%2,%3}, [%4];"
        : "=r"(r0), "=r"(r1), "=r"(r2), "=r"(r3) : "r"(addr));
}
__device__ __forceinline__ void ldsm4t(unsigned& r0, unsigned& r1, unsigned& r2, unsigned& r3,
                                       uint32_t addr) {
    asm volatile("ldmatrix.sync.aligned.m8n8.x4.trans.shared.b16 {%0,%1,%2,%3}, [%4];"
        : "=r"(r0), "=r"(r1), "=r"(r2), "=r"(r3) : "r"(addr));
}

// ============================================================
// fp32 -> fp16 conversion of x and the 4 weight matrices (once)
// ============================================================
struct CvtArgs {
    const float* x; const float* w0; const float* w1; const float* w2; const float* w3;
};
#define X_U4   (N_TOK * D_MODEL / 4)
#define W_U4   (D_MODEL * D_MODEL / 4)

__global__ void cvt_kernel(CvtArgs a) {
    int i = blockIdx.x * blockDim.x + threadIdx.x;
    const float* src; __half* dst; int k;
    if (i < X_U4) { src = a.x; dst = g_xh; k = i; }
    else {
        int j = i - X_U4;
        int w = j >> 16;
        k = j & 65535;
        src = (w == 0) ? a.w0 : (w == 1) ? a.w1 : (w == 2) ? a.w2 : a.w3;
        dst = g_Wh[w];
    }
    float4 v = ((const float4*)src)[k];
    ((uint2*)dst)[k] = make_uint2(h2u(v.x, v.y), h2u(v.z, v.w));
}

// ============================================================
// Pairwise distance, fp16, lane-ordered: [q][kblk(64)][t(4)][nt(8)][e(2)]
// ============================================================
__global__ void dist_kernel(const float* __restrict__ coords, __half* __restrict__ distH) {
    int idx = blockIdx.x * blockDim.x + threadIdx.x;   // over 4096*2048 half2s
    int i = idx >> 11;
    int r = idx & 2047;
    int blk = r >> 5;
    int w = r & 31;
    int t = w >> 3, nt = w & 7;
    int j0 = blk * 64 + nt * 8 + 2 * t;
    float cx = coords[2 * i], cy = coords[2 * i + 1];
    float2 c0 = *(const float2*)&coords[2 * j0];
    float2 c1 = *(const float2*)&coords[2 * j0 + 2];
    float dx0 = cx - c0.x, dy0 = cy - c0.y;
    float dx1 = cx - c1.x, dy1 = cy - c1.y;
    float d0 = sqrt_ap(__fmaf_rn(dy0, dy0, dx0 * dx0));
    float d1 = sqrt_ap(__fmaf_rn(dy1, dy1, dx1 * dx1));
    ((__half2*)distH)[idx] = __floats2half2_rn(d0, d1);
}

// ============================================================
// GEMM fp16-in (unchanged): m16n8k16, ldmatrix, double-buffered
// ============================================================
struct GemmArgs { const __half* W; const float* bias; void* C; float scale; int half_out; };
struct GemmArgs3 { GemmArgs a[3]; };

#define GBUFB (128 * GPH * 2)

__global__ __launch_bounds__(256, 2) void gemm128h(
    const __half* __restrict__ A, GemmArgs3 args) {
    const GemmArgs ga = args.a[blockIdx.z];
    const __half* __restrict__ W = ga.W;
    const float* __restrict__ bias = ga.bias;

    __shared__ __half sA[2][128 * GPH];
    __shared__ __half sW[2][128 * GPH];

    const int m0 = blockIdx.x * 128, n0 = blockIdx.y * 128;
    const int tid = threadIdx.x;
    const int warp = tid >> 5, lane = tid & 31;
    const int g = lane >> 2, t = lane & 3;
    const int wm = warp >> 1, wn = warp & 1;

    const int lr = tid >> 3;
    const int lc = (tid & 7) << 2;

    const uint32_t baseA = (uint32_t)__cvta_generic_to_shared(&sA[0][0])
        + ((wm * 32 + (lane & 15)) * GPH + ((lane & 16) >> 1)) * 2;
    const uint32_t baseW = (uint32_t)__cvta_generic_to_shared(&sW[0][0])
        + ((wn * 64 + (lane & 7) + ((lane & 16) >> 1)) * GPH + (lane & 8)) * 2;

    uint2 ra[4], rw[4];
#pragma unroll
    for (int p = 0; p < 4; p++) {
        ra[p] = *(const uint2*)&A[(size_t)(m0 + lr + p * 32) * D_MODEL + lc];
        rw[p] = *(const uint2*)&W[(size_t)(n0 + lr + p * 32) * D_MODEL + lc];
    }

    float acc[2][8][4];
#pragma unroll
    for (int mt = 0; mt < 2; mt++)
#pragma unroll
        for (int nt = 0; nt < 8; nt++)
#pragma unroll
            for (int e = 0; e < 4; e++) acc[mt][nt][e] = 0.f;

#pragma unroll
    for (int p = 0; p < 4; p++) {
        *(uint2*)&sA[0][(lr + p * 32) * GPH + lc] = ra[p];
        *(uint2*)&sW[0][(lr + p * 32) * GPH + lc] = rw[p];
    }
    __syncthreads();

    for (int ks = 0; ks < 16; ks++) {
        const int cur = ks & 1;
        if (ks < 15) {
            int kt = (ks + 1) * 32;
#pragma unroll
            for (int p = 0; p < 4; p++) {
                ra[p] = *(const uint2*)&A[(size_t)(m0 + lr + p * 32) * D_MODEL + kt + lc];
                rw[p] = *(const uint2*)&W[(size_t)(n0 + lr + p * 32) * D_MODEL + kt + lc];
            }
        }

#pragma unroll
        for (int kc = 0; kc < 2; kc++) {
            unsigned a0[2], a1[2], a2[2], a3[2];
#pragma unroll
            for (int mt = 0; mt < 2; mt++)
                ldsm4(a0[mt], a1[mt], a2[mt], a3[mt],
                      baseA + cur * GBUFB + mt * (16 * GPH * 2) + kc * 32);
#pragma unroll
            for (int np = 0; np < 4; np++) {
                unsigned b0, b1, b2, b3;
                ldsm4(b0, b1, b2, b3,
                      baseW + cur * GBUFB + np * (16 * GPH * 2) + kc * 32);
#pragma unroll
                for (int mt = 0; mt < 2; mt++) {
                    mma_f16(acc[mt][2 * np],     a0[mt], a1[mt], a2[mt], a3[mt], b0, b1);
                    mma_f16(acc[mt][2 * np + 1], a0[mt], a1[mt], a2[mt], a3[mt], b2, b3);
                }
            }
        }

        if (ks < 15) {
            const int nxt = cur ^ 1;
#pragma unroll
            for (int p = 0; p < 4; p++) {
                *(uint2*)&sA[nxt][(lr + p * 32) * GPH + lc] = ra[p];
                *(uint2*)&sW[nxt][(lr + p * 32) * GPH + lc] = rw[p];
            }
        }
        __syncthreads();
    }

    if (ga.half_out) {
        __half* C = (__half*)ga.C;
        const float sc = ga.scale;
#pragma unroll
        for (int nt = 0; nt < 8; nt++) {
            int col = n0 + wn * 64 + nt * 8 + 2 * t;
            float2 bb = *(const float2*)&bias[col];
#pragma unroll
            for (int mt = 0; mt < 2; mt++) {
                int r0 = m0 + wm * 32 + mt * 16 + g;
                *(unsigned*)&C[(size_t)r0 * D_MODEL + col] =
                    h2u((acc[mt][nt][0] + bb.x) * sc, (acc[mt][nt][1] + bb.y) * sc);
                *(unsigned*)&C[(size_t)(r0 + 8) * D_MODEL + col] =
                    h2u((acc[mt][nt][2] + bb.x) * sc, (acc[mt][nt][3] + bb.y) * sc);
            }
        }
    } else {
        float* C = (float*)ga.C;
#pragma unroll
        for (int nt = 0; nt < 8; nt++) {
            int col = n0 + wn * 64 + nt * 8 + 2 * t;
            float2 bb = *(const float2*)&bias[col];
#pragma unroll
            for (int mt = 0; mt < 2; mt++) {
                int r0 = m0 + wm * 32 + mt * 16 + g;
                *(float2*)&C[(size_t)r0 * D_MODEL + col] =
                    make_float2(acc[mt][nt][0] + bb.x, acc[mt][nt][1] + bb.y);
                *(float2*)&C[(size_t)(r0 + 8) * D_MODEL + col] =
                    make_float2(acc[mt][nt][2] + bb.x, acc[mt][nt][3] + bb.y);
            }
        }
    }
}

// ============================================================
// Flash attention v10: 4 warps, M=32/warp, Q fragments cached in
// registers (loaded once), K/V double-buffered in smem with ONE
// __syncthreads per iteration. fp16 m16n8k16, static-max softmax,
// precomputed lane-ordered fp16 distances.
// smem: sK[2][64][HP], sV[2][64][HP] = 36 KB (Q staged through sK).
// ============================================================
__global__ __launch_bounds__(128) void flash10(
    const __half* __restrict__ Qg, const __half* __restrict__ Kg,
    const __half* __restrict__ Vg, const __half* __restrict__ distH,
    __half* __restrict__ Og) {
    extern __shared__ char smraw[];
    __half* sK0 = (__half*)smraw;            // K buffers [2][64][HP]
    __half* sV0 = sK0 + 2 * KBUF;            // V buffers [2][64][HP]

    const int tid = threadIdx.x;
    const int warp = tid >> 5, lane = tid & 31;
    const int g = lane >> 2, t = lane & 3;
    const int q0 = blockIdx.x * 128;
    const int h  = blockIdx.y;
    const float LOG2E = 1.44269504f;
    const float slope2 = exp2f(-(float)(h + 1)) * LOG2E;

    const int qr0 = q0 + warp * 32 + g;      // rows qr0, +8 (mt0), +16, +24 (mt1)

    // dist row pointers (halves): [q][kblk][t][nt][e]
    const __half* dR0 = distH + ((size_t)qr0 * N_TOK) + t * 16;
    const __half* dR1 = dR0 + (size_t)8  * N_TOK;
    const __half* dR2 = dR0 + (size_t)16 * N_TOK;
    const __half* dR3 = dR0 + (size_t)24 * N_TOK;

    const uint32_t smemK = (uint32_t)__cvta_generic_to_shared(sK0);
    const uint32_t smemV = (uint32_t)__cvta_generic_to_shared(sV0);
    const uint32_t baseK = smemK
        + (((lane & 7) + ((lane & 16) >> 1)) * HP + (lane & 8)) * 2;
    const uint32_t baseV = smemV
        + ((lane & 15) * HP + ((lane & 16) >> 1)) * 2;

    // ---- stage Q through the K buffers, capture fragments in registers ----
    // rows 0..63 -> sK0 area, rows 64..127 -> sK1 area
    for (int i = tid; i < 128 * 16; i += 128) {
        int r = i >> 4, cu = (i & 15) << 2;
        __half* dst = (r < 64) ? &sK0[r * HP + cu] : &sK0[KBUF + (r - 64) * HP + cu];
        *(uint2*)dst = *(const uint2*)&Qg[(size_t)(q0 + r) * D_MODEL + h * DH + cu];
    }
    __syncthreads();
    unsigned qf[4][2][4];   // [kc][mt][reg]
    {
        // warp w covers q rows w*32..w*32+31; local row in buffer = (warp&1)*32 + ...
        uint32_t qb = smemK + (warp >> 1) * KBUFB
            + (((warp & 1) * 32 + (lane & 15)) * HP + ((lane & 16) >> 1)) * 2;
#pragma unroll
        for (int kc = 0; kc < 4; kc++)
#pragma unroll
            for (int mt = 0; mt < 2; mt++)
                ldsm4(qf[kc][mt][0], qf[kc][mt][1], qf[kc][mt][2], qf[kc][mt][3],
                      qb + mt * (16 * HP * 2) + kc * 32);
    }
    __syncthreads();   // Q staging reads done; buffers free for K

    float o[2][8][4];
#pragma unroll
    for (int mt = 0; mt < 2; mt++)
#pragma unroll
        for (int nt = 0; nt < 8; nt++) {
            o[mt][nt][0] = o[mt][nt][1] = o[mt][nt][2] = o[mt][nt][3] = 0.f;
        }
    float lp00 = 0.f, lp01 = 0.f, lp10 = 0.f, lp11 = 0.f;

    // ---- K/V loader mapping: 128 threads x 8 steps cover 64 rows x 16 uint2 ----
    const int kr = tid >> 4;            // 0..7 (+8p)
    const int kb = (tid & 15) << 2;     // half offset

    // prologue: load tile 0 into buffer 0
    {
        uint2 kre[8], vre[8];
#pragma unroll
        for (int p = 0; p < 8; p++) {
            kre[p] = *(const uint2*)&Kg[(size_t)(kr + p * 8) * D_MODEL + h * DH + kb];
            vre[p] = *(const uint2*)&Vg[(size_t)(kr + p * 8) * D_MODEL + h * DH + kb];
        }
#pragma unroll
        for (int p = 0; p < 8; p++) {
            *(uint2*)&sK0[(kr + p * 8) * HP + kb] = kre[p];
            *(uint2*)&sV0[(kr + p * 8) * HP + kb] = vre[p];
        }
    }
    __syncthreads();

    for (int k0 = 0; k0 < N_TOK; k0 += 64) {
        const int cur = (k0 >> 6) & 1;
        const int nxt = cur ^ 1;

        // issue next-tile global loads (into regs; stored after softmax)
        uint2 kre[8], vre[8];
        if (k0 + 64 < N_TOK) {
#pragma unroll
            for (int p = 0; p < 8; p++) {
                kre[p] = *(const uint2*)&Kg[(size_t)(k0 + 64 + kr + p * 8) * D_MODEL + h * DH + kb];
                vre[p] = *(const uint2*)&Vg[(size_t)(k0 + 64 + kr + p * 8) * D_MODEL + h * DH + kb];
            }
        }

        // dist loads (mt0 rows)
        uint4 d0a = *(const uint4*)(dR0 + k0);
        uint4 d0b = *(const uint4*)(dR0 + k0 + 8);
        uint4 d1a = *(const uint4*)(dR1 + k0);
        uint4 d1b = *(const uint4*)(dR1 + k0 + 8);

        // ---- S = Q @ K^T (Q from registers), accumulators pre-biased ----
        float s[2][8][4];
#pragma unroll
        for (int mt = 0; mt < 2; mt++)
#pragma unroll
            for (int nt = 0; nt < 8; nt++) {
                s[mt][nt][0] = -SMAX; s[mt][nt][1] = -SMAX;
                s[mt][nt][2] = -SMAX; s[mt][nt][3] = -SMAX;
            }
#pragma unroll
        for (int kc = 0; kc < 4; kc++) {
#pragma unroll
            for (int np = 0; np < 4; np++) {
                unsigned b0, b1, b2, b3;
                ldsm4(b0, b1, b2, b3, baseK + cur * KBUFB + np * 2304 + kc * 32);
#pragma unroll
                for (int mt = 0; mt < 2; mt++) {
                    mma_f16(s[mt][2 * np],     qf[kc][mt][0], qf[kc][mt][1],
                            qf[kc][mt][2], qf[kc][mt][3], b0, b1);
                    mma_f16(s[mt][2 * np + 1], qf[kc][mt][0], qf[kc][mt][1],
                            qf[kc][mt][2], qf[kc][mt][3], b2, b3);
                }
            }
        }

        // dist loads (mt1 rows)
        uint4 d2a = *(const uint4*)(dR2 + k0);
        uint4 d2b = *(const uint4*)(dR2 + k0 + 8);
        uint4 d3a = *(const uint4*)(dR3 + k0);
        uint4 d3b = *(const uint4*)(dR3 + k0 + 8);

        // ---- P = exp2(S - SMAX - slope*dist); per-lane l ----
#pragma unroll
        for (int nt = 0; nt < 8; nt++) {
            __half2 h0 = ((const __half2*)(nt < 4 ? &d0a : &d0b))[nt & 3];
            __half2 h1 = ((const __half2*)(nt < 4 ? &d1a : &d1b))[nt & 3];
            float2 f0 = __half22float2(h0);
            float2 f1 = __half22float2(h1);
            float p0 = ex2f(__fmaf_rn(-slope2, f0.x, s[0][nt][0]));
            float p1 = ex2f(__fmaf_rn(-slope2, f0.y, s[0][nt][1]));
            float p2 = ex2f(__fmaf_rn(-slope2, f1.x, s[0][nt][2]));
            float p3 = ex2f(__fmaf_rn(-slope2, f1.y, s[0][nt][3]));
            s[0][nt][0] = p0; s[0][nt][1] = p1; s[0][nt][2] = p2; s[0][nt][3] = p3;
            lp00 += p0 + p1;
            lp01 += p2 + p3;
        }
#pragma unroll
        for (int nt = 0; nt < 8; nt++) {
            __half2 h2v = ((const __half2*)(nt < 4 ? &d2a : &d2b))[nt & 3];
            __half2 h3v = ((const __half2*)(nt < 4 ? &d3a : &d3b))[nt & 3];
            float2 f2 = __half22float2(h2v);
            float2 f3 = __half22float2(h3v);
            float p0 = ex2f(__fmaf_rn(-slope2, f2.x, s[1][nt][0]));
            float p1 = ex2f(__fmaf_rn(-slope2, f2.y, s[1][nt][1]));
            float p2 = ex2f(__fmaf_rn(-slope2, f3.x, s[1][nt][2]));
            float p3 = ex2f(__fmaf_rn(-slope2, f3.y, s[1][nt][3]));
            s[1][nt][0] = p0; s[1][nt][1] = p1; s[1][nt][2] = p2; s[1][nt][3] = p3;
            lp10 += p0 + p1;
            lp11 += p2 + p3;
        }

        // store next K/V tile into the other buffers (hidden under PV)
        if (k0 + 64 < N_TOK) {
#pragma unroll
            for (int p = 0; p < 8; p++) {
                *(uint2*)&sK0[nxt * KBUF + (kr + p * 8) * HP + kb] = kre[p];
                *(uint2*)&sV0[nxt * KBUF + (kr + p * 8) * HP + kb] = vre[p];
            }
        }

        // ---- O += P @ V (reads cur V buffer) ----
#pragma unroll
        for (int kc = 0; kc < 4; kc++) {
            unsigned a0[2], a1[2], a2[2], a3[2];
#pragma unroll
            for (int mt = 0; mt < 2; mt++) {
                a0[mt] = h2u(s[mt][2 * kc][0],     s[mt][2 * kc][1]);
                a1[mt] = h2u(s[mt][2 * kc][2],     s[mt][2 * kc][3]);
                a2[mt] = h2u(s[mt][2 * kc + 1][0], s[mt][2 * kc + 1][1]);
                a3[mt] = h2u(s[mt][2 * kc + 1][2], s[mt][2 * kc + 1][3]);
            }
#pragma unroll
            for (int np = 0; np < 4; np++) {
                unsigned v0, v1, v2, v3;
                ldsm4t(v0, v1, v2, v3, baseV + cur * KBUFB + kc * 2304 + np * 32);
#pragma unroll
                for (int mt = 0; mt < 2; mt++) {
                    mma_f16(o[mt][2 * np],     a0[mt], a1[mt], a2[mt], a3[mt], v0, v1);
                    mma_f16(o[mt][2 * np + 1], a0[mt], a1[mt], a2[mt], a3[mt], v2, v3);
                }
            }
        }

        __syncthreads();   // ONE barrier: cur fully read, nxt fully written
    }

    // ---- epilogue: reduce l across the t-quad, normalize, store fp16 ----
    lp00 += __shfl_xor_sync(0xffffffffu, lp00, 1);
    lp00 += __shfl_xor_sync(0xffffffffu, lp00, 2);
    lp01 += __shfl_xor_sync(0xffffffffu, lp01, 1);
    lp01 += __shfl_xor_sync(0xffffffffu, lp01, 2);
    lp10 += __shfl_xor_sync(0xffffffffu, lp10, 1);
    lp10 += __shfl_xor_sync(0xffffffffu, lp10, 2);
    lp11 += __shfl_xor_sync(0xffffffffu, lp11, 1);
    lp11 += __shfl_xor_sync(0xffffffffu, lp11, 2);
    float inv00 = 1.f / lp00, inv01 = 1.f / lp01;
    float inv10 = 1.f / lp10, inv11 = 1.f / lp11;
#pragma unroll
    for (int nt = 0; nt < 8; nt++) {
        int col = h * DH + nt * 8 + 2 * t;
        *(unsigned*)&Og[(size_t)qr0 * D_MODEL + col] =
            h2u(o[0][nt][0] * inv00, o[0][nt][1] * inv00);
        *(unsigned*)&Og[(size_t)(qr0 + 8) * D_MODEL + col] =
            h2u(o[0][nt][2] * inv01, o[0][nt][3] * inv01);
        *(unsigned*)&Og[(size_t)(qr0 + 16) * D_MODEL + col] =
            h2u(o[1][nt][0] * inv10, o[1][nt][1] * inv10);
        *(unsigned*)&Og[(size_t)(qr0 + 24) * D_MODEL + col] =
            h2u(o[1][nt][2] * inv11, o[1][nt][3] * inv11);
    }
}

// ============================================================
// launcher
// ============================================================
extern "C" void kernel_launch(void* const* d_in, const int* in_sizes, int n_in,
                              void* d_out, int out_size) {
    const float* x      = (const float*)d_in[0];
    const float* coords = (const float*)d_in[1];
    const float* Wq = (const float*)d_in[2]; const float* bq = (const float*)d_in[3];
    const float* Wk = (const float*)d_in[4]; const float* bk = (const float*)d_in[5];
    const float* Wv = (const float*)d_in[6]; const float* bv = (const float*)d_in[7];
    const float* Wo = (const float*)d_in[8]; const float* bo = (const float*)d_in[9];
    float* out = (float*)d_out;

    __half *pxh, *pWh, *pQh, *pKh, *pVh, *pAOh, *pD;
    cudaGetSymbolAddress((void**)&pxh, g_xh);
    cudaGetSymbolAddress((void**)&pWh, g_Wh);
    cudaGetSymbolAddress((void**)&pQh, g_Qh);
    cudaGetSymbolAddress((void**)&pKh, g_Kh);
    cudaGetSymbolAddress((void**)&pVh, g_Vh);
    cudaGetSymbolAddress((void**)&pAOh, g_AOh);
    cudaGetSymbolAddress((void**)&pD, g_distH);
    const size_t WSTRIDE = (size_t)D_MODEL * D_MODEL;

    const size_t FLASH_SMEM = (size_t)4 * KBUF * sizeof(__half);   // 36 KB
    cudaFuncSetAttribute(flash10, cudaFuncAttributeMaxDynamicSharedMemorySize, (int)FLASH_SMEM);

    // 1. convert x + weights to fp16
    CvtArgs ca = { x, Wq, Wk, Wv, Wo };
    cvt_kernel<<<(X_U4 + 4 * W_U4) / 256, 256>>>(ca);

    // 2. distance matrix (fp16, lane-ordered)
    dist_kernel<<<(N_TOK * N_TOK / 2) / 256, 256>>>(coords, pD);

    // 3. QKV projections (fp16 out; Q pre-scaled by qscale = 0.125*log2e)
    const float qscale = 0.125f * 1.44269504f;
    GemmArgs3 qkv;
    qkv.a[0] = { pWh + 0 * WSTRIDE, bq, pQh, qscale, 1 };
    qkv.a[1] = { pWh + 1 * WSTRIDE, bk, pKh, 1.0f,   1 };
    qkv.a[2] = { pWh + 2 * WSTRIDE, bv, pVh, 1.0f,   1 };
    gemm128h<<<dim3(N_TOK / 128, D_MODEL / 128, 3), 256>>>(pxh, qkv);

    // 4. flash attention (4 warps, M=32/warp, 1 sync/iter)
    flash10<<<dim3(N_TOK / 128, NH), 128, FLASH_SMEM>>>(pQh, pKh, pVh, pD, pAOh);

    // 5. output projection (fp32 out)
    GemmArgs3 og;
    og.a[0] = { pWh + 3 * WSTRIDE, bo, out, 1.0f, 0 };
    og.a[1] = og.a[0]; og.a[2] = og.a[0];
    gemm128h<<<dim3(N_TOK / 128, D_MODEL / 128, 1), 256>>>(pAOh, og);
}

// round 17
// speedup vs baseline: 1.0508x; 1.0508x over previous
#include <cuda_runtime.h>
#include <cuda_fp16.h>
#include <cstdint>

#define N_TOK 4096
#define D_MODEL 512
#define NH 8
#define DH 64
#define HP 72       // flash fp16 smem row pitch (halves)
#define GPH 40      // gemm fp16 smem row pitch (halves)
#define SMAX 16.0f  // static softmax max (log2 domain)
#define KBUF (64 * HP)          // halves per K/V buffer
#define KBUFB (KBUF * 2)        // bytes per buffer (9216)

// ---- device scratch (no cudaMalloc allowed) ----
__device__ __half g_xh[(size_t)N_TOK * D_MODEL];
__device__ __half g_Wh[4][(size_t)D_MODEL * D_MODEL];   // Wq, Wk, Wv, Wo
__device__ __half g_Qh[(size_t)N_TOK * D_MODEL];        // pre-scaled by qscale
__device__ __half g_Kh[(size_t)N_TOK * D_MODEL];
__device__ __half g_Vh[(size_t)N_TOK * D_MODEL];
__device__ __half g_AOh[(size_t)N_TOK * D_MODEL];
__device__ __half g_distH[(size_t)N_TOK * N_TOK];       // lane-ordered fp16 distances

// ============================================================
// helpers
// ============================================================
__device__ __forceinline__ float ex2f(float x) {
    float y;
    asm("ex2.approx.f32 %0, %1;" : "=f"(y) : "f"(x));
    return y;
}
__device__ __forceinline__ float sqrt_ap(float x) {
    float y;
    asm("sqrt.approx.f32 %0, %1;" : "=f"(y) : "f"(x));
    return y;
}
__device__ __forceinline__ unsigned h2u(float x, float y) {
    __half2 h = __floats2half2_rn(x, y);
    return *reinterpret_cast<unsigned*>(&h);
}

// fp16 m16n8k16, fp32 accum
__device__ __forceinline__ void mma_f16(float d[4],
    unsigned a0, unsigned a1, unsigned a2, unsigned a3,
    unsigned b0, unsigned b1) {
    asm volatile(
        "mma.sync.aligned.m16n8k16.row.col.f32.f16.f16.f32 "
        "{%0,%1,%2,%3},{%4,%5,%6,%7},{%8,%9},{%0,%1,%2,%3};\n"
        : "+f"(d[0]), "+f"(d[1]), "+f"(d[2]), "+f"(d[3])
        : "r"(a0), "r"(a1), "r"(a2), "r"(a3), "r"(b0), "r"(b1));
}

__device__ __forceinline__ void ldsm4(unsigned& r0, unsigned& r1, unsigned& r2, unsigned& r3,
                                      uint32_t addr) {
    asm volatile("ldmatrix.sync.aligned.m8n8.x4.shared.b16 {%0,%1,%2,%3}, [%4];"
        : "=r"(r0), "=r"(r1), "=r"(r2), "=r"(r3) : "r"(addr));
}
__device__ __forceinline__ void ldsm4t(unsigned& r0, unsigned& r1, unsigned& r2, unsigned& r3,
                                       uint32_t addr) {
    asm volatile("ldmatrix.sync.aligned.m8n8.x4.trans.shared.b16 {%0,%1,%2,%3}, [%4];"
        : "=r"(r0), "=r"(r1), "=r"(r2), "=r"(r3) : "r"(addr));
}

__device__ __forceinline__ void cp_async16(uint32_t dst, const void* src) {
    asm volatile("cp.async.cg.shared.global [%0], [%1], 16;" :: "r"(dst), "l"(src));
}
#define CP_COMMIT() asm volatile("cp.async.commit_group;")
#define CP_WAIT0()  asm volatile("cp.async.wait_group 0;")

// ============================================================
// fp32 -> fp16 conversion of x and the 4 weight matrices (once)
// ============================================================
struct CvtArgs {
    const float* x; const float* w0; const float* w1; const float* w2; const float* w3;
};
#define X_U4   (N_TOK * D_MODEL / 4)
#define W_U4   (D_MODEL * D_MODEL / 4)

__global__ void cvt_kernel(CvtArgs a) {
    int i = blockIdx.x * blockDim.x + threadIdx.x;
    const float* src; __half* dst; int k;
    if (i < X_U4) { src = a.x; dst = g_xh; k = i; }
    else {
        int j = i - X_U4;
        int w = j >> 16;
        k = j & 65535;
        src = (w == 0) ? a.w0 : (w == 1) ? a.w1 : (w == 2) ? a.w2 : a.w3;
        dst = g_Wh[w];
    }
    float4 v = ((const float4*)src)[k];
    ((uint2*)dst)[k] = make_uint2(h2u(v.x, v.y), h2u(v.z, v.w));
}

// ============================================================
// Pairwise distance, fp16, lane-ordered: [q][kblk(64)][t(4)][nt(8)][e(2)]
// ============================================================
__global__ void dist_kernel(const float* __restrict__ coords, __half* __restrict__ distH) {
    int idx = blockIdx.x * blockDim.x + threadIdx.x;   // over 4096*2048 half2s
    int i = idx >> 11;
    int r = idx & 2047;
    int blk = r >> 5;
    int w = r & 31;
    int t = w >> 3, nt = w & 7;
    int j0 = blk * 64 + nt * 8 + 2 * t;
    float cx = coords[2 * i], cy = coords[2 * i + 1];
    float2 c0 = *(const float2*)&coords[2 * j0];
    float2 c1 = *(const float2*)&coords[2 * j0 + 2];
    float dx0 = cx - c0.x, dy0 = cy - c0.y;
    float dx1 = cx - c1.x, dy1 = cy - c1.y;
    float d0 = sqrt_ap(__fmaf_rn(dy0, dy0, dx0 * dx0));
    float d1 = sqrt_ap(__fmaf_rn(dy1, dy1, dx1 * dx1));
    ((__half2*)distH)[idx] = __floats2half2_rn(d0, d1);
}

// ============================================================
// GEMM fp16-in (unchanged): m16n8k16, ldmatrix, double-buffered
// ============================================================
struct GemmArgs { const __half* W; const float* bias; void* C; float scale; int half_out; };
struct GemmArgs3 { GemmArgs a[3]; };

#define GBUFB (128 * GPH * 2)

__global__ __launch_bounds__(256, 2) void gemm128h(
    const __half* __restrict__ A, GemmArgs3 args) {
    const GemmArgs ga = args.a[blockIdx.z];
    const __half* __restrict__ W = ga.W;
    const float* __restrict__ bias = ga.bias;

    __shared__ __half sA[2][128 * GPH];
    __shared__ __half sW[2][128 * GPH];

    const int m0 = blockIdx.x * 128, n0 = blockIdx.y * 128;
    const int tid = threadIdx.x;
    const int warp = tid >> 5, lane = tid & 31;
    const int g = lane >> 2, t = lane & 3;
    const int wm = warp >> 1, wn = warp & 1;

    const int lr = tid >> 3;
    const int lc = (tid & 7) << 2;

    const uint32_t baseA = (uint32_t)__cvta_generic_to_shared(&sA[0][0])
        + ((wm * 32 + (lane & 15)) * GPH + ((lane & 16) >> 1)) * 2;
    const uint32_t baseW = (uint32_t)__cvta_generic_to_shared(&sW[0][0])
        + ((wn * 64 + (lane & 7) + ((lane & 16) >> 1)) * GPH + (lane & 8)) * 2;

    uint2 ra[4], rw[4];
#pragma unroll
    for (int p = 0; p < 4; p++) {
        ra[p] = *(const uint2*)&A[(size_t)(m0 + lr + p * 32) * D_MODEL + lc];
        rw[p] = *(const uint2*)&W[(size_t)(n0 + lr + p * 32) * D_MODEL + lc];
    }

    float acc[2][8][4];
#pragma unroll
    for (int mt = 0; mt < 2; mt++)
#pragma unroll
        for (int nt = 0; nt < 8; nt++)
#pragma unroll
            for (int e = 0; e < 4; e++) acc[mt][nt][e] = 0.f;

#pragma unroll
    for (int p = 0; p < 4; p++) {
        *(uint2*)&sA[0][(lr + p * 32) * GPH + lc] = ra[p];
        *(uint2*)&sW[0][(lr + p * 32) * GPH + lc] = rw[p];
    }
    __syncthreads();

    for (int ks = 0; ks < 16; ks++) {
        const int cur = ks & 1;
        if (ks < 15) {
            int kt = (ks + 1) * 32;
#pragma unroll
            for (int p = 0; p < 4; p++) {
                ra[p] = *(const uint2*)&A[(size_t)(m0 + lr + p * 32) * D_MODEL + kt + lc];
                rw[p] = *(const uint2*)&W[(size_t)(n0 + lr + p * 32) * D_MODEL + kt + lc];
            }
        }

#pragma unroll
        for (int kc = 0; kc < 2; kc++) {
            unsigned a0[2], a1[2], a2[2], a3[2];
#pragma unroll
            for (int mt = 0; mt < 2; mt++)
                ldsm4(a0[mt], a1[mt], a2[mt], a3[mt],
                      baseA + cur * GBUFB + mt * (16 * GPH * 2) + kc * 32);
#pragma unroll
            for (int np = 0; np < 4; np++) {
                unsigned b0, b1, b2, b3;
                ldsm4(b0, b1, b2, b3,
                      baseW + cur * GBUFB + np * (16 * GPH * 2) + kc * 32);
#pragma unroll
                for (int mt = 0; mt < 2; mt++) {
                    mma_f16(acc[mt][2 * np],     a0[mt], a1[mt], a2[mt], a3[mt], b0, b1);
                    mma_f16(acc[mt][2 * np + 1], a0[mt], a1[mt], a2[mt], a3[mt], b2, b3);
                }
            }
        }

        if (ks < 15) {
            const int nxt = cur ^ 1;
#pragma unroll
            for (int p = 0; p < 4; p++) {
                *(uint2*)&sA[nxt][(lr + p * 32) * GPH + lc] = ra[p];
                *(uint2*)&sW[nxt][(lr + p * 32) * GPH + lc] = rw[p];
            }
        }
        __syncthreads();
    }

    if (ga.half_out) {
        __half* C = (__half*)ga.C;
        const float sc = ga.scale;
#pragma unroll
        for (int nt = 0; nt < 8; nt++) {
            int col = n0 + wn * 64 + nt * 8 + 2 * t;
            float2 bb = *(const float2*)&bias[col];
#pragma unroll
            for (int mt = 0; mt < 2; mt++) {
                int r0 = m0 + wm * 32 + mt * 16 + g;
                *(unsigned*)&C[(size_t)r0 * D_MODEL + col] =
                    h2u((acc[mt][nt][0] + bb.x) * sc, (acc[mt][nt][1] + bb.y) * sc);
                *(unsigned*)&C[(size_t)(r0 + 8) * D_MODEL + col] =
                    h2u((acc[mt][nt][2] + bb.x) * sc, (acc[mt][nt][3] + bb.y) * sc);
            }
        }
    } else {
        float* C = (float*)ga.C;
#pragma unroll
        for (int nt = 0; nt < 8; nt++) {
            int col = n0 + wn * 64 + nt * 8 + 2 * t;
            float2 bb = *(const float2*)&bias[col];
#pragma unroll
            for (int mt = 0; mt < 2; mt++) {
                int r0 = m0 + wm * 32 + mt * 16 + g;
                *(float2*)&C[(size_t)r0 * D_MODEL + col] =
                    make_float2(acc[mt][nt][0] + bb.x, acc[mt][nt][1] + bb.y);
                *(float2*)&C[(size_t)(r0 + 8) * D_MODEL + col] =
                    make_float2(acc[mt][nt][2] + bb.x, acc[mt][nt][3] + bb.y);
            }
        }
    }
}

// ============================================================
// Flash attention v11: 4 warps, M=32/warp, Q fragments in registers,
// K/V double-buffered via cp.async (NO register staging), 1 barrier +
// 1 wait_group per iteration. fp16 m16n8k16, static-max softmax,
// precomputed lane-ordered fp16 distances.
// smem: sK[2][64][HP], sV[2][64][HP] = 36 KB (Q staged through idle bufs).
// ============================================================
__global__ __launch_bounds__(128) void flash11(
    const __half* __restrict__ Qg, const __half* __restrict__ Kg,
    const __half* __restrict__ Vg, const __half* __restrict__ distH,
    __half* __restrict__ Og) {
    extern __shared__ char smraw[];
    __half* sK0 = (__half*)smraw;            // K buffers [2][64][HP]
    __half* sV0 = sK0 + 2 * KBUF;            // V buffers [2][64][HP]

    const int tid = threadIdx.x;
    const int warp = tid >> 5, lane = tid & 31;
    const int g = lane >> 2, t = lane & 3;
    const int q0 = blockIdx.x * 128;
    const int h  = blockIdx.y;
    const float LOG2E = 1.44269504f;
    const float slope2 = exp2f(-(float)(h + 1)) * LOG2E;

    const int qr0 = q0 + warp * 32 + g;      // rows qr0, +8 (mt0), +16, +24 (mt1)

    // dist row pointers (halves): [q][kblk][t][nt][e]
    const __half* dR0 = distH + ((size_t)qr0 * N_TOK) + t * 16;
    const __half* dR1 = dR0 + (size_t)8  * N_TOK;
    const __half* dR2 = dR0 + (size_t)16 * N_TOK;
    const __half* dR3 = dR0 + (size_t)24 * N_TOK;

    const uint32_t smemK = (uint32_t)__cvta_generic_to_shared(sK0);
    const uint32_t smemV = (uint32_t)__cvta_generic_to_shared(sV0);
    const uint32_t baseK = smemK
        + (((lane & 7) + ((lane & 16) >> 1)) * HP + (lane & 8)) * 2;
    const uint32_t baseV = smemV
        + ((lane & 15) * HP + ((lane & 16) >> 1)) * 2;

    // ---- cp.async loader mapping: 16B chunks; 64 rows x 8 chunks ----
    const int crow = tid >> 3;          // 0..15 (+16p)
    const int coff = (tid & 7) * 8;     // half offset of 16B chunk

    // ---- prologue A: issue cp.async for K/V tile 0 into buffer 0 ----
#pragma unroll
    for (int p = 0; p < 4; p++) {
        int row = crow + p * 16;
        cp_async16(smemK + (row * HP + coff) * 2,
                   &Kg[(size_t)row * D_MODEL + h * DH + coff]);
        cp_async16(smemV + (row * HP + coff) * 2,
                   &Vg[(size_t)row * D_MODEL + h * DH + coff]);
    }
    CP_COMMIT();

    // ---- prologue B: stage Q through the IDLE second buffers (K1, V1) ----
    for (int i = tid; i < 128 * 16; i += 128) {
        int r = i >> 4, cu = (i & 15) << 2;
        __half* dst = (r < 64) ? &sK0[KBUF + r * HP + cu]
                               : &sV0[KBUF + (r - 64) * HP + cu];
        *(uint2*)dst = *(const uint2*)&Qg[(size_t)(q0 + r) * D_MODEL + h * DH + cu];
    }
    __syncthreads();
    unsigned qf[4][2][4];   // [kc][mt][reg]
    {
        // warps 0,1 rows 0..63 in K1; warps 2,3 rows 64..127 in V1
        uint32_t qb = ((warp < 2) ? smemK : smemV) + KBUFB
            + (((warp & 1) * 32 + (lane & 15)) * HP + ((lane & 16) >> 1)) * 2;
#pragma unroll
        for (int kc = 0; kc < 4; kc++)
#pragma unroll
            for (int mt = 0; mt < 2; mt++)
                ldsm4(qf[kc][mt][0], qf[kc][mt][1], qf[kc][mt][2], qf[kc][mt][3],
                      qb + mt * (16 * HP * 2) + kc * 32);
    }
    // (no barrier needed here: buffer-1 writes happen in iter 0 AFTER its
    //  top barrier, which orders them against these reads)

    float o[2][8][4];
#pragma unroll
    for (int mt = 0; mt < 2; mt++)
#pragma unroll
        for (int nt = 0; nt < 8; nt++) {
            o[mt][nt][0] = o[mt][nt][1] = o[mt][nt][2] = o[mt][nt][3] = 0.f;
        }
    float lp00 = 0.f, lp01 = 0.f, lp10 = 0.f, lp11 = 0.f;

    for (int k0 = 0; k0 < N_TOK; k0 += 64) {
        const int cur = (k0 >> 6) & 1;
        const int nxt = cur ^ 1;

        CP_WAIT0();        // cur tile data arrived (this thread's groups)
        __syncthreads();   // all threads' arrivals + prior-iter reads done

        // issue cp.async for next tile into nxt buffers
        if (k0 + 64 < N_TOK) {
#pragma unroll
            for (int p = 0; p < 4; p++) {
                int row = crow + p * 16;
                cp_async16(smemK + (nxt * KBUF + row * HP + coff) * 2,
                           &Kg[(size_t)(k0 + 64 + row) * D_MODEL + h * DH + coff]);
                cp_async16(smemV + (nxt * KBUF + row * HP + coff) * 2,
                           &Vg[(size_t)(k0 + 64 + row) * D_MODEL + h * DH + coff]);
            }
            CP_COMMIT();
        }

        // dist loads (mt0 rows)
        uint4 d0a = *(const uint4*)(dR0 + k0);
        uint4 d0b = *(const uint4*)(dR0 + k0 + 8);
        uint4 d1a = *(const uint4*)(dR1 + k0);
        uint4 d1b = *(const uint4*)(dR1 + k0 + 8);

        // ---- S = Q @ K^T (Q from registers), accumulators pre-biased ----
        float s[2][8][4];
#pragma unroll
        for (int mt = 0; mt < 2; mt++)
#pragma unroll
            for (int nt = 0; nt < 8; nt++) {
                s[mt][nt][0] = -SMAX; s[mt][nt][1] = -SMAX;
                s[mt][nt][2] = -SMAX; s[mt][nt][3] = -SMAX;
            }
#pragma unroll
        for (int kc = 0; kc < 4; kc++) {
#pragma unroll
            for (int np = 0; np < 4; np++) {
                unsigned b0, b1, b2, b3;
                ldsm4(b0, b1, b2, b3, baseK + cur * KBUFB + np * 2304 + kc * 32);
#pragma unroll
                for (int mt = 0; mt < 2; mt++) {
                    mma_f16(s[mt][2 * np],     qf[kc][mt][0], qf[kc][mt][1],
                            qf[kc][mt][2], qf[kc][mt][3], b0, b1);
                    mma_f16(s[mt][2 * np + 1], qf[kc][mt][0], qf[kc][mt][1],
                            qf[kc][mt][2], qf[kc][mt][3], b2, b3);
                }
            }
        }

        // dist loads (mt1 rows)
        uint4 d2a = *(const uint4*)(dR2 + k0);
        uint4 d2b = *(const uint4*)(dR2 + k0 + 8);
        uint4 d3a = *(const uint4*)(dR3 + k0);
        uint4 d3b = *(const uint4*)(dR3 + k0 + 8);

        // ---- P = exp2(S - SMAX - slope*dist); per-lane l ----
#pragma unroll
        for (int nt = 0; nt < 8; nt++) {
            __half2 h0 = ((const __half2*)(nt < 4 ? &d0a : &d0b))[nt & 3];
            __half2 h1 = ((const __half2*)(nt < 4 ? &d1a : &d1b))[nt & 3];
            float2 f0 = __half22float2(h0);
            float2 f1 = __half22float2(h1);
            float p0 = ex2f(__fmaf_rn(-slope2, f0.x, s[0][nt][0]));
            float p1 = ex2f(__fmaf_rn(-slope2, f0.y, s[0][nt][1]));
            float p2 = ex2f(__fmaf_rn(-slope2, f1.x, s[0][nt][2]));
            float p3 = ex2f(__fmaf_rn(-slope2, f1.y, s[0][nt][3]));
            s[0][nt][0] = p0; s[0][nt][1] = p1; s[0][nt][2] = p2; s[0][nt][3] = p3;
            lp00 += p0 + p1;
            lp01 += p2 + p3;
        }
#pragma unroll
        for (int nt = 0; nt < 8; nt++) {
            __half2 h2v = ((const __half2*)(nt < 4 ? &d2a : &d2b))[nt & 3];
            __half2 h3v = ((const __half2*)(nt < 4 ? &d3a : &d3b))[nt & 3];
            float2 f2 = __half22float2(h2v);
            float2 f3 = __half22float2(h3v);
            float p0 = ex2f(__fmaf_rn(-slope2, f2.x, s[1][nt][0]));
            float p1 = ex2f(__fmaf_rn(-slope2, f2.y, s[1][nt][1]));
            float p2 = ex2f(__fmaf_rn(-slope2, f3.x, s[1][nt][2]));
            float p3 = ex2f(__fmaf_rn(-slope2, f3.y, s[1][nt][3]));
            s[1][nt][0] = p0; s[1][nt][1] = p1; s[1][nt][2] = p2; s[1][nt][3] = p3;
            lp10 += p0 + p1;
            lp11 += p2 + p3;
        }

        // ---- O += P @ V (reads cur V buffer) ----
#pragma unroll
        for (int kc = 0; kc < 4; kc++) {
            unsigned a0[2], a1[2], a2[2], a3[2];
#pragma unroll
            for (int mt = 0; mt < 2; mt++) {
                a0[mt] = h2u(s[mt][2 * kc][0],     s[mt][2 * kc][1]);
                a1[mt] = h2u(s[mt][2 * kc][2],     s[mt][2 * kc][3]);
                a2[mt] = h2u(s[mt][2 * kc + 1][0], s[mt][2 * kc + 1][1]);
                a3[mt] = h2u(s[mt][2 * kc + 1][2], s[mt][2 * kc + 1][3]);
            }
#pragma unroll
            for (int np = 0; np < 4; np++) {
                unsigned v0, v1, v2, v3;
                ldsm4t(v0, v1, v2, v3, baseV + cur * KBUFB + kc * 2304 + np * 32);
#pragma unroll
                for (int mt = 0; mt < 2; mt++) {
                    mma_f16(o[mt][2 * np],     a0[mt], a1[mt], a2[mt], a3[mt], v0, v1);
                    mma_f16(o[mt][2 * np + 1], a0[mt], a1[mt], a2[mt], a3[mt], v2, v3);
                }
            }
        }
    }

    // ---- epilogue: reduce l across the t-quad, normalize, store fp16 ----
    lp00 += __shfl_xor_sync(0xffffffffu, lp00, 1);
    lp00 += __shfl_xor_sync(0xffffffffu, lp00, 2);
    lp01 += __shfl_xor_sync(0xffffffffu, lp01, 1);
    lp01 += __shfl_xor_sync(0xffffffffu, lp01, 2);
    lp10 += __shfl_xor_sync(0xffffffffu, lp10, 1);
    lp10 += __shfl_xor_sync(0xffffffffu, lp10, 2);
    lp11 += __shfl_xor_sync(0xffffffffu, lp11, 1);
    lp11 += __shfl_xor_sync(0xffffffffu, lp11, 2);
    float inv00 = 1.f / lp00, inv01 = 1.f / lp01;
    float inv10 = 1.f / lp10, inv11 = 1.f / lp11;
#pragma unroll
    for (int nt = 0; nt < 8; nt++) {
        int col = h * DH + nt * 8 + 2 * t;
        *(unsigned*)&Og[(size_t)qr0 * D_MODEL + col] =
            h2u(o[0][nt][0] * inv00, o[0][nt][1] * inv00);
        *(unsigned*)&Og[(size_t)(qr0 + 8) * D_MODEL + col] =
            h2u(o[0][nt][2] * inv01, o[0][nt][3] * inv01);
        *(unsigned*)&Og[(size_t)(qr0 + 16) * D_MODEL + col] =
            h2u(o[1][nt][0] * inv10, o[1][nt][1] * inv10);
        *(unsigned*)&Og[(size_t)(qr0 + 24) * D_MODEL + col] =
            h2u(o[1][nt][2] * inv11, o[1][nt][3] * inv11);
    }
}

// ============================================================
// launcher
// ============================================================
extern "C" void kernel_launch(void* const* d_in, const int* in_sizes, int n_in,
                              void* d_out, int out_size) {
    const float* x      = (const float*)d_in[0];
    const float* coords = (const float*)d_in[1];
    const float* Wq = (const float*)d_in[2]; const float* bq = (const float*)d_in[3];
    const float* Wk = (const float*)d_in[4]; const float* bk = (const float*)d_in[5];
    const float* Wv = (const float*)d_in[6]; const float* bv = (const float*)d_in[7];
    const float* Wo = (const float*)d_in[8]; const float* bo = (const float*)d_in[9];
    float* out = (float*)d_out;

    __half *pxh, *pWh, *pQh, *pKh, *pVh, *pAOh, *pD;
    cudaGetSymbolAddress((void**)&pxh, g_xh);
    cudaGetSymbolAddress((void**)&pWh, g_Wh);
    cudaGetSymbolAddress((void**)&pQh, g_Qh);
    cudaGetSymbolAddress((void**)&pKh, g_Kh);
    cudaGetSymbolAddress((void**)&pVh, g_Vh);
    cudaGetSymbolAddress((void**)&pAOh, g_AOh);
    cudaGetSymbolAddress((void**)&pD, g_distH);
    const size_t WSTRIDE = (size_t)D_MODEL * D_MODEL;

    const size_t FLASH_SMEM = (size_t)4 * KBUF * sizeof(__half);   // 36 KB
    cudaFuncSetAttribute(flash11, cudaFuncAttributeMaxDynamicSharedMemorySize, (int)FLASH_SMEM);

    // 1. convert x + weights to fp16
    CvtArgs ca = { x, Wq, Wk, Wv, Wo };
    cvt_kernel<<<(X_U4 + 4 * W_U4) / 256, 256>>>(ca);

    // 2. distance matrix (fp16, lane-ordered)
    dist_kernel<<<(N_TOK * N_TOK / 2) / 256, 256>>>(coords, pD);

    // 3. QKV projections (fp16 out; Q pre-scaled by qscale = 0.125*log2e)
    const float qscale = 0.125f * 1.44269504f;
    GemmArgs3 qkv;
    qkv.a[0] = { pWh + 0 * WSTRIDE, bq, pQh, qscale, 1 };
    qkv.a[1] = { pWh + 1 * WSTRIDE, bk, pKh, 1.0f,   1 };
    qkv.a[2] = { pWh + 2 * WSTRIDE, bv, pVh, 1.0f,   1 };
    gemm128h<<<dim3(N_TOK / 128, D_MODEL / 128, 3), 256>>>(pxh, qkv);

    // 4. flash attention (4 warps, M=32/warp, cp.async double-buffer)
    flash11<<<dim3(N_TOK / 128, NH), 128, FLASH_SMEM>>>(pQh, pKh, pVh, pD, pAOh);

    // 5. output projection (fp32 out)
    GemmArgs3 og;
    og.a[0] = { pWh + 3 * WSTRIDE, bo, out, 1.0f, 0 };
    og.a[1] = og.a[0]; og.a[2] = og.a[0];
    gemm128h<<<dim3(N_TOK / 128, D_MODEL / 128, 1), 256>>>(pAOh, og);
}